// round 1
// baseline (speedup 1.0000x reference)
#include <cuda_runtime.h>

#define BATCH 4096
#define F 32
#define C 128
#define K1 32
#define K2 496
#define K3 4960
#define KTOT (K1 + K2 + K3)   // 5488

#define TM 64
#define TN 128
#define KB 16
#define NTHREADS 256
#define SPLITK 4
#define NCHUNK (KTOT / KB)    // 343  (all segment boundaries are multiples of KB)

// Deterministic split-K partials: scratch[s][b][c]
__device__ float g_scratch[SPLITK * BATCH * C];

__global__ __launch_bounds__(NTHREADS) void fused_interact_gemm(
    const float* __restrict__ x,
    const float* __restrict__ W1, const float* __restrict__ W2, const float* __restrict__ W3,
    const int* __restrict__ idx1, const int* __restrict__ idx2, const int* __restrict__ idx3)
{
    __shared__ float xs[TM][F + 2];   // col F holds 1.0f (identity for missing indices)
    __shared__ float Ps[KB][TM + 4];  // +4 pad: conflict-free STS.128 on writes
    __shared__ float Ws[KB][TN];

    const int tid = threadIdx.x;
    const int b0  = blockIdx.x * TM;

    // ---- load x tile (64 rows x 32 cols), vectorized ----
    for (int t = tid; t < TM * (F / 4); t += NTHREADS) {
        int r  = t >> 3;       // F/4 == 8 float4 per row
        int c4 = t & 7;
        float4 v = reinterpret_cast<const float4*>(x + (size_t)(b0 + r) * F)[c4];
        xs[r][c4 * 4 + 0] = v.x;
        xs[r][c4 * 4 + 1] = v.y;
        xs[r][c4 * 4 + 2] = v.z;
        xs[r][c4 * 4 + 3] = v.w;
    }
    for (int r = tid; r < TM; r += NTHREADS) xs[r][F] = 1.0f;

    // ---- split-K chunk range ----
    const int s     = blockIdx.y;
    const int c_beg = (s * NCHUNK) / SPLITK;
    const int c_end = ((s + 1) * NCHUNK) / SPLITK;

    float acc[4][8];
#pragma unroll
    for (int i = 0; i < 4; i++)
#pragma unroll
        for (int j = 0; j < 8; j++) acc[i][j] = 0.0f;

    const int ty = tid >> 4;          // 0..15  -> rows ty*4 .. ty*4+3
    const int tx = tid & 15;          // 0..15  -> cols tx*8 .. tx*8+7
    const int pk = tid & 15;          // combo-in-chunk this thread computes products for
    const int pr = (tid >> 4) * 4;    // 4 rows of products

    __syncthreads();                  // x tile ready

    for (int ch = c_beg; ch < c_end; ++ch) {
        const int k0 = ch * KB;

        // segment select (uniform across CTA: chunks never straddle segments)
        const float* Wseg;
        int krel;
        int order;
        if (k0 < K1)           { Wseg = W1; krel = k0;            order = 1; }
        else if (k0 < K1 + K2) { Wseg = W2; krel = k0 - K1;       order = 2; }
        else                   { Wseg = W3; krel = k0 - K1 - K2;  order = 3; }

        // gather combo indices for this thread's combo (missing -> F = ones column)
        int i0, i1, i2;
        if (order == 3) {
            const int* ip = idx3 + (size_t)(krel + pk) * 3;
            i0 = ip[0]; i1 = ip[1]; i2 = ip[2];
        } else if (order == 2) {
            const int* ip = idx2 + (size_t)(krel + pk) * 2;
            i0 = ip[0]; i1 = ip[1]; i2 = F;
        } else {
            i0 = idx1[krel + pk]; i1 = F; i2 = F;
        }

        __syncthreads();  // previous chunk's FMA loop done before overwriting Ps/Ws

        // stage W chunk: 16x128 floats = 512 float4, 2 per thread, coalesced
        {
            const float4* src = reinterpret_cast<const float4*>(Wseg + (size_t)krel * C);
            float4* dst = reinterpret_cast<float4*>(&Ws[0][0]);
            dst[tid]            = src[tid];
            dst[tid + NTHREADS] = src[tid + NTHREADS];
        }

        // compute P chunk: 4 products per thread, one STS.128 (pad keeps it conflict-free)
        {
            float4 p;
            p.x = xs[pr + 0][i0] * xs[pr + 0][i1] * xs[pr + 0][i2];
            p.y = xs[pr + 1][i0] * xs[pr + 1][i1] * xs[pr + 1][i2];
            p.z = xs[pr + 2][i0] * xs[pr + 2][i1] * xs[pr + 2][i2];
            p.w = xs[pr + 3][i0] * xs[pr + 3][i1] * xs[pr + 3][i2];
            *reinterpret_cast<float4*>(&Ps[pk][pr]) = p;
        }

        __syncthreads();  // Ps/Ws ready

        // 64x128 tile FMA: per thread 4x8 rank-1 updates over KB k's
#pragma unroll
        for (int k = 0; k < KB; ++k) {
            float4 p  = *reinterpret_cast<const float4*>(&Ps[k][ty * 4]);
            float4 wa = *reinterpret_cast<const float4*>(&Ws[k][tx * 8]);
            float4 wb = *reinterpret_cast<const float4*>(&Ws[k][tx * 8 + 4]);
            acc[0][0] += p.x * wa.x; acc[0][1] += p.x * wa.y; acc[0][2] += p.x * wa.z; acc[0][3] += p.x * wa.w;
            acc[0][4] += p.x * wb.x; acc[0][5] += p.x * wb.y; acc[0][6] += p.x * wb.z; acc[0][7] += p.x * wb.w;
            acc[1][0] += p.y * wa.x; acc[1][1] += p.y * wa.y; acc[1][2] += p.y * wa.z; acc[1][3] += p.y * wa.w;
            acc[1][4] += p.y * wb.x; acc[1][5] += p.y * wb.y; acc[1][6] += p.y * wb.z; acc[1][7] += p.y * wb.w;
            acc[2][0] += p.z * wa.x; acc[2][1] += p.z * wa.y; acc[2][2] += p.z * wa.z; acc[2][3] += p.z * wa.w;
            acc[2][4] += p.z * wb.x; acc[2][5] += p.z * wb.y; acc[2][6] += p.z * wb.z; acc[2][7] += p.z * wb.w;
            acc[3][0] += p.w * wa.x; acc[3][1] += p.w * wa.y; acc[3][2] += p.w * wa.z; acc[3][3] += p.w * wa.w;
            acc[3][4] += p.w * wb.x; acc[3][5] += p.w * wb.y; acc[3][6] += p.w * wb.z; acc[3][7] += p.w * wb.w;
        }
    }

    // ---- epilogue: write deterministic split-K partials (every element written exactly once) ----
    float* base = g_scratch + (size_t)s * BATCH * C;
#pragma unroll
    for (int i = 0; i < 4; i++) {
        int row = b0 + ty * 4 + i;
        float* op = base + (size_t)row * C + tx * 8;
        float4 v0 = make_float4(acc[i][0], acc[i][1], acc[i][2], acc[i][3]);
        float4 v1 = make_float4(acc[i][4], acc[i][5], acc[i][6], acc[i][7]);
        reinterpret_cast<float4*>(op)[0] = v0;
        reinterpret_cast<float4*>(op)[1] = v1;
    }
}

__global__ void reduce_out(const float* __restrict__ bias, float* __restrict__ out)
{
    int i = blockIdx.x * blockDim.x + threadIdx.x;   // over B*C/4 float4
    const int n4 = BATCH * C / 4;
    if (i < n4) {
        float4 b  = reinterpret_cast<const float4*>(bias)[i & (C / 4 - 1)];
        const float4* s0 = reinterpret_cast<const float4*>(g_scratch);
        const float4* s1 = reinterpret_cast<const float4*>(g_scratch + (size_t)1 * BATCH * C);
        const float4* s2 = reinterpret_cast<const float4*>(g_scratch + (size_t)2 * BATCH * C);
        const float4* s3 = reinterpret_cast<const float4*>(g_scratch + (size_t)3 * BATCH * C);
        float4 a0 = s0[i], a1 = s1[i], a2 = s2[i], a3 = s3[i];
        float4 r;
        r.x = b.x + ((a0.x + a1.x) + (a2.x + a3.x));
        r.y = b.y + ((a0.y + a1.y) + (a2.y + a3.y));
        r.z = b.z + ((a0.z + a1.z) + (a2.z + a3.z));
        r.w = b.w + ((a0.w + a1.w) + (a2.w + a3.w));
        reinterpret_cast<float4*>(out)[i] = r;
    }
}

extern "C" void kernel_launch(void* const* d_in, const int* in_sizes, int n_in,
                              void* d_out, int out_size)
{
    const float* x    = (const float*)d_in[0];
    const float* bias = (const float*)d_in[1];
    const float* W1   = (const float*)d_in[2];
    const float* W2   = (const float*)d_in[3];
    const float* W3   = (const float*)d_in[4];
    const int*   idx1 = (const int*)d_in[5];
    const int*   idx2 = (const int*)d_in[6];
    const int*   idx3 = (const int*)d_in[7];
    float* out = (float*)d_out;

    dim3 grid(BATCH / TM, SPLITK);
    fused_interact_gemm<<<grid, NTHREADS>>>(x, W1, W2, W3, idx1, idx2, idx3);

    int n4 = BATCH * C / 4;
    reduce_out<<<(n4 + 255) / 256, 256>>>(bias, out);
}

// round 2
// speedup vs baseline: 1.2084x; 1.2084x over previous
#include <cuda_runtime.h>

#define BATCH 4096
#define F 32
#define C 128
#define K1 32
#define K2 496
#define K3 4960
#define KTOT (K1 + K2 + K3)   // 5488

#define TM 128
#define TN 128
#define KB 16
#define NTHREADS 256
#define SPLITK 9
#define NCHUNK (KTOT / KB)    // 343  (segment boundaries 32/528/5488 are multiples of 16)

// Deterministic split-K partials: scratch[s][b][c]
__device__ float g_scratch[SPLITK * BATCH * C];

__global__ __launch_bounds__(NTHREADS, 2) void fused_interact_gemm(
    const float* __restrict__ x,
    const float* __restrict__ W1, const float* __restrict__ W2, const float* __restrict__ W3,
    const int* __restrict__ idx1, const int* __restrict__ idx2, const int* __restrict__ idx3)
{
    __shared__ float xs[TM][F + 2];    // col F holds 1.0f (identity for missing indices)
    __shared__ float Ps[KB][TM + 4];   // +4 pad: conflict-free STS.128
    __shared__ float Ws[KB][TN];

    const int tid = threadIdx.x;
    const int b0  = blockIdx.x * TM;

    // ---- load x tile (128 rows x 32 cols), vectorized, + ones column ----
    for (int t = tid; t < TM * (F / 4); t += NTHREADS) {
        int r  = t >> 3;        // 8 float4 per row
        int c4 = t & 7;
        float4 v = reinterpret_cast<const float4*>(x + (size_t)(b0 + r) * F)[c4];
        xs[r][c4 * 4 + 0] = v.x;
        xs[r][c4 * 4 + 1] = v.y;
        xs[r][c4 * 4 + 2] = v.z;
        xs[r][c4 * 4 + 3] = v.w;
    }
    for (int r = tid; r < TM; r += NTHREADS) xs[r][F] = 1.0f;

    // ---- split-K chunk range ----
    const int s     = blockIdx.y;
    const int c_beg = (s * NCHUNK) / SPLITK;
    const int c_end = ((s + 1) * NCHUNK) / SPLITK;

    float acc[8][8];
#pragma unroll
    for (int i = 0; i < 8; i++)
#pragma unroll
        for (int j = 0; j < 8; j++) acc[i][j] = 0.0f;

    const int ty = tid >> 4;          // 0..15 -> rows ty*8 .. ty*8+7
    const int tx = tid & 15;          // 0..15 -> cols tx*4..+3 and 64+tx*4..+3
    const int pk = tid & 15;          // combo-in-chunk this thread computes products for
    const int pr = (tid >> 4) * 8;    // 8 rows of products

    // ---- prefetch state (W chunk in regs + this thread's combo indices) ----
    int   i0, i1, i2;
    float4 w0, w1;

    auto prefetch = [&](int ch) {
        const int k0 = ch * KB;
        const float* Wseg;
        int krel;
        if (k0 < K1) {
            Wseg = W1; krel = k0;
            i0 = idx1[krel + pk]; i1 = F; i2 = F;
        } else if (k0 < K1 + K2) {
            Wseg = W2; krel = k0 - K1;
            const int* ip = idx2 + (size_t)(krel + pk) * 2;
            i0 = ip[0]; i1 = ip[1]; i2 = F;
        } else {
            Wseg = W3; krel = k0 - K1 - K2;
            const int* ip = idx3 + (size_t)(krel + pk) * 3;
            i0 = ip[0]; i1 = ip[1]; i2 = ip[2];
        }
        const float4* src = reinterpret_cast<const float4*>(Wseg + (size_t)krel * C);
        w0 = src[tid];
        w1 = src[tid + NTHREADS];
    };

    prefetch(c_beg);
    __syncthreads();   // xs ready

    for (int ch = c_beg; ch < c_end; ++ch) {
        // products for this chunk (reads xs only; regs)
        float pv[8];
#pragma unroll
        for (int j = 0; j < 8; j++)
            pv[j] = xs[pr + j][i0] * xs[pr + j][i1] * xs[pr + j][i2];

        __syncthreads();   // consumers done with previous Ps/Ws

        // stage W chunk from regs + P chunk
        {
            float4* dst = reinterpret_cast<float4*>(&Ws[0][0]);
            dst[tid]            = w0;
            dst[tid + NTHREADS] = w1;
            *reinterpret_cast<float4*>(&Ps[pk][pr])     = make_float4(pv[0], pv[1], pv[2], pv[3]);
            *reinterpret_cast<float4*>(&Ps[pk][pr + 4]) = make_float4(pv[4], pv[5], pv[6], pv[7]);
        }

        __syncthreads();   // Ps/Ws ready

        // issue next chunk's global loads early (latency hides under FMA block)
        if (ch + 1 < c_end) prefetch(ch + 1);

        // 128x128 tile FMA: per thread 8x8 rank-1 updates over KB k's
#pragma unroll
        for (int k = 0; k < KB; ++k) {
            float4 pa = *reinterpret_cast<const float4*>(&Ps[k][ty * 8]);
            float4 pb = *reinterpret_cast<const float4*>(&Ps[k][ty * 8 + 4]);
            float4 wa = *reinterpret_cast<const float4*>(&Ws[k][tx * 4]);
            float4 wb = *reinterpret_cast<const float4*>(&Ws[k][64 + tx * 4]);
            float p[8] = {pa.x, pa.y, pa.z, pa.w, pb.x, pb.y, pb.z, pb.w};
            float w[8] = {wa.x, wa.y, wa.z, wa.w, wb.x, wb.y, wb.z, wb.w};
#pragma unroll
            for (int i = 0; i < 8; i++)
#pragma unroll
                for (int j = 0; j < 8; j++)
                    acc[i][j] += p[i] * w[j];
        }
    }

    // ---- epilogue: deterministic split-K partials (each element written once) ----
    float* base = g_scratch + ((size_t)s * BATCH + b0) * C;
#pragma unroll
    for (int i = 0; i < 8; i++) {
        float* rowp = base + (size_t)(ty * 8 + i) * C;
        reinterpret_cast<float4*>(rowp + tx * 4)[0]      = make_float4(acc[i][0], acc[i][1], acc[i][2], acc[i][3]);
        reinterpret_cast<float4*>(rowp + 64 + tx * 4)[0] = make_float4(acc[i][4], acc[i][5], acc[i][6], acc[i][7]);
    }
}

__global__ void reduce_out(const float* __restrict__ bias, float* __restrict__ out)
{
    int i = blockIdx.x * blockDim.x + threadIdx.x;   // over B*C/4 float4
    const int n4 = BATCH * C / 4;
    if (i < n4) {
        float4 b = reinterpret_cast<const float4*>(bias)[i & (C / 4 - 1)];
        float sx = b.x, sy = b.y, sz = b.z, sw = b.w;
#pragma unroll
        for (int s = 0; s < SPLITK; s++) {
            float4 a = reinterpret_cast<const float4*>(g_scratch + (size_t)s * BATCH * C)[i];
            sx += a.x; sy += a.y; sz += a.z; sw += a.w;
        }
        reinterpret_cast<float4*>(out)[i] = make_float4(sx, sy, sz, sw);
    }
}

extern "C" void kernel_launch(void* const* d_in, const int* in_sizes, int n_in,
                              void* d_out, int out_size)
{
    const float* x    = (const float*)d_in[0];
    const float* bias = (const float*)d_in[1];
    const float* W1   = (const float*)d_in[2];
    const float* W2   = (const float*)d_in[3];
    const float* W3   = (const float*)d_in[4];
    const int*   idx1 = (const int*)d_in[5];
    const int*   idx2 = (const int*)d_in[6];
    const int*   idx3 = (const int*)d_in[7];
    float* out = (float*)d_out;

    dim3 grid(BATCH / TM, SPLITK);
    fused_interact_gemm<<<grid, NTHREADS>>>(x, W1, W2, W3, idx1, idx2, idx3);

    int n4 = BATCH * C / 4;
    reduce_out<<<(n4 + 255) / 256, 256>>>(bias, out);
}

// round 4
// speedup vs baseline: 2.1011x; 1.7388x over previous
#include <cuda_runtime.h>
#include <cstdint>

#define BATCH 4096
#define F 32
#define C 128
#define K1 32
#define K2 496
#define K3 4960
#define KTOT 5488
#define KPAD 5504               // 172 * 32
#define KB 32                   // K per staged chunk = 4 mma k-steps of 8
#define NCH (KPAD / KB)         // 172
#define SPLITK 4
#define NCH_S (NCH / SPLITK)    // 43
#define TM 128
#define NT 256

// smem layout in floats
#define PS_STRIDE 36            // (4*row + k) mod 32 conflict-free
#define WS_STRIDE 36
#define SM_PS 0
#define SM_WS (128 * PS_STRIDE)               // 4608
#define SM_XS (SM_WS + 128 * WS_STRIDE)       // 9216
#define SMEM_FLOATS (SM_XS + 128 * 33)        // 13440
#define SMEM_BYTES (SMEM_FLOATS * 4)          // 53760

__device__ float g_Wt[(size_t)C * KPAD];               // W^T, tf32-rounded, k-contiguous
__device__ float g_scratch[(size_t)SPLITK * BATCH * C];

__device__ __forceinline__ float tf32_rna(float v) {
    uint32_t r;
    asm("cvt.rna.tf32.f32 %0, %1;" : "=r"(r) : "f"(v));
    return __uint_as_float(r);
}

__device__ __forceinline__ void mma_tf32(float* c, const uint32_t* a, uint32_t b0, uint32_t b1) {
    asm volatile(
        "mma.sync.aligned.m16n8k8.row.col.f32.tf32.tf32.f32 "
        "{%0,%1,%2,%3}, {%4,%5,%6,%7}, {%8,%9}, {%0,%1,%2,%3};"
        : "+f"(c[0]), "+f"(c[1]), "+f"(c[2]), "+f"(c[3])
        : "r"(a[0]), "r"(a[1]), "r"(a[2]), "r"(a[3]), "r"(b0), "r"(b1));
}

// ---------------- kernel 1: W -> g_Wt[c][k], tf32-rounded ----------------
__global__ void transpose_W(const float* __restrict__ W1,
                            const float* __restrict__ W2,
                            const float* __restrict__ W3)
{
    __shared__ float t[32][33];
    const int kt = blockIdx.x * 32, ct = blockIdx.y * 32;
    const int tx = threadIdx.x, ty = threadIdx.y;   // 32 x 8
#pragma unroll
    for (int j = 0; j < 32; j += 8) {
        int k = kt + ty + j;
        float v = 0.0f;
        if (k < KTOT) {
            const float* p;
            if (k < K1)            p = W1 + (size_t)k * C;
            else if (k < K1 + K2)  p = W2 + (size_t)(k - K1) * C;
            else                   p = W3 + (size_t)(k - (K1 + K2)) * C;
            v = p[ct + tx];
        }
        t[ty + j][tx] = tf32_rna(v);
    }
    __syncthreads();
#pragma unroll
    for (int j = 0; j < 32; j += 8) {
        int c = ct + ty + j;
        g_Wt[(size_t)c * KPAD + kt + tx] = t[tx][ty + j];
    }
}

// ---------------- kernel 2: warp-mma tf32 GEMM, P computed on the fly ----------------
__global__ void __launch_bounds__(NT, 1) gemm_mma(
    const float* __restrict__ x,
    const int* __restrict__ idx1, const int* __restrict__ idx2, const int* __restrict__ idx3)
{
    extern __shared__ float sm[];
    float* Ps = sm + SM_PS;     // [128][36] tf32 products, row-major in k
    float* Ws = sm + SM_WS;     // [128 n][36 k] tf32 weights
    float* xs = sm + SM_XS;     // [128][33], col 32 = 1.0f

    const int tid  = threadIdx.x;
    const int b0   = blockIdx.x * TM;
    const int s    = blockIdx.y;
    const int lane = tid & 31;
    const int wid  = tid >> 5;
    const int gid  = lane >> 2;   // 0..7
    const int tg   = lane & 3;    // 0..3
    const int wm   = wid >> 1;    // 0..3 -> warp rows wm*32
    const int wn   = wid & 1;     // 0..1 -> warp cols wn*64

    // ---- x tile + ones column ----
    for (int t = tid; t < TM * (F / 4); t += NT) {
        int r = t >> 3, c4 = t & 7;
        float4 v = reinterpret_cast<const float4*>(x + (size_t)(b0 + r) * F)[c4];
        xs[r * 33 + c4 * 4 + 0] = v.x;
        xs[r * 33 + c4 * 4 + 1] = v.y;
        xs[r * 33 + c4 * 4 + 2] = v.z;
        xs[r * 33 + c4 * 4 + 3] = v.w;
    }
    if (tid < TM) xs[tid * 33 + F] = 1.0f;

    // staging roles
    const int kk    = tid & 31;          // k-in-chunk this thread produces
    const int rbase = (tid >> 5) * 16;   // 16 rows of products

    float4 w[4];
    float  pv[16];

    auto prefetch = [&](int c) {
        const int kbase = (s * NCH_S + c) * KB;
        // W chunk: 4096 floats = 1024 float4, 4 per thread, coalesced 128B runs
#pragma unroll
        for (int q = 0; q < 4; ++q) {
            int v = tid + q * NT;
            int n = v >> 3, kq = v & 7;
            w[q] = *reinterpret_cast<const float4*>(g_Wt + (size_t)n * KPAD + kbase + kq * 4);
        }
        // products for k = kbase+kk, rows rbase..rbase+15
        const int kg = kbase + kk;
        int i0 = F, i1 = F, i2 = F;
        const bool live = kg < KTOT;
        if (live) {
            if (kg < K1)           { i0 = idx1[kg]; }
            else if (kg < K1 + K2) { const int* ip = idx2 + (size_t)(kg - K1) * 2;
                                     i0 = ip[0]; i1 = ip[1]; }
            else                   { const int* ip = idx3 + (size_t)(kg - (K1 + K2)) * 3;
                                     i0 = ip[0]; i1 = ip[1]; i2 = ip[2]; }
        }
#pragma unroll
        for (int j = 0; j < 16; ++j) {
            int r = rbase + j;
            float p = live ? xs[r * 33 + i0] * xs[r * 33 + i1] * xs[r * 33 + i2] : 0.0f;
            pv[j] = tf32_rna(p);
        }
    };

    auto stage = [&]() {
#pragma unroll
        for (int q = 0; q < 4; ++q) {
            int v = tid + q * NT;
            int n = v >> 3, kq = v & 7;
            *reinterpret_cast<float4*>(Ws + n * WS_STRIDE + kq * 4) = w[q];
        }
#pragma unroll
        for (int j = 0; j < 16; ++j)
            Ps[(rbase + j) * PS_STRIDE + kk] = pv[j];
    };

    float cfr[2][8][4];
#pragma unroll
    for (int mb = 0; mb < 2; ++mb)
#pragma unroll
        for (int nb = 0; nb < 8; ++nb)
#pragma unroll
            for (int q = 0; q < 4; ++q) cfr[mb][nb][q] = 0.0f;

    __syncthreads();          // xs ready
    prefetch(0);
    stage();
    __syncthreads();          // chunk 0 staged

    const uint32_t* pu = reinterpret_cast<const uint32_t*>(Ps);
    const uint32_t* wu = reinterpret_cast<const uint32_t*>(Ws);

    for (int c = 0; c < NCH_S; ++c) {
        if (c + 1 < NCH_S) prefetch(c + 1);   // LDG + products hide under mma

#pragma unroll
        for (int ks = 0; ks < 4; ++ks) {
            const int acol = ks * 8 + tg;
            uint32_t A[2][4];
#pragma unroll
            for (int mb = 0; mb < 2; ++mb) {
                int r = wm * 32 + mb * 16 + gid;
                A[mb][0] = pu[(r)     * PS_STRIDE + acol];
                A[mb][1] = pu[(r + 8) * PS_STRIDE + acol];
                A[mb][2] = pu[(r)     * PS_STRIDE + acol + 4];
                A[mb][3] = pu[(r + 8) * PS_STRIDE + acol + 4];
            }
#pragma unroll
            for (int nb = 0; nb < 8; ++nb) {
                int n = wn * 64 + nb * 8 + gid;
                uint32_t B0 = wu[n * WS_STRIDE + ks * 8 + tg];
                uint32_t B1 = wu[n * WS_STRIDE + ks * 8 + tg + 4];
                mma_tf32(cfr[0][nb], A[0], B0, B1);
                mma_tf32(cfr[1][nb], A[1], B0, B1);
            }
        }

        __syncthreads();                       // all warps done with smem chunk
        if (c + 1 < NCH_S) {
            stage();
            __syncthreads();                   // next chunk visible
        }
    }

    // ---- epilogue: deterministic split-K partials ----
    float* dst = g_scratch + ((size_t)s * BATCH + b0) * C;
#pragma unroll
    for (int mb = 0; mb < 2; ++mb) {
        int r = wm * 32 + mb * 16 + gid;
#pragma unroll
        for (int nb = 0; nb < 8; ++nb) {
            int col = wn * 64 + nb * 8 + 2 * tg;
            *reinterpret_cast<float2*>(dst + (size_t)r * C + col) =
                make_float2(cfr[mb][nb][0], cfr[mb][nb][1]);
            *reinterpret_cast<float2*>(dst + (size_t)(r + 8) * C + col) =
                make_float2(cfr[mb][nb][2], cfr[mb][nb][3]);
        }
    }
}

// ---------------- kernel 3: split-K reduce + bias ----------------
__global__ void reduce_out(const float* __restrict__ bias, float* __restrict__ out)
{
    int i = blockIdx.x * blockDim.x + threadIdx.x;
    const int n4 = BATCH * C / 4;
    if (i < n4) {
        float4 b = reinterpret_cast<const float4*>(bias)[i & (C / 4 - 1)];
        float sx = b.x, sy = b.y, sz = b.z, sw = b.w;
#pragma unroll
        for (int s = 0; s < SPLITK; s++) {
            float4 a = reinterpret_cast<const float4*>(g_scratch + (size_t)s * BATCH * C)[i];
            sx += a.x; sy += a.y; sz += a.z; sw += a.w;
        }
        reinterpret_cast<float4*>(out)[i] = make_float4(sx, sy, sz, sw);
    }
}

extern "C" void kernel_launch(void* const* d_in, const int* in_sizes, int n_in,
                              void* d_out, int out_size)
{
    const float* x    = (const float*)d_in[0];
    const float* bias = (const float*)d_in[1];
    const float* W1   = (const float*)d_in[2];
    const float* W2   = (const float*)d_in[3];
    const float* W3   = (const float*)d_in[4];
    const int*   idx1 = (const int*)d_in[5];
    const int*   idx2 = (const int*)d_in[6];
    const int*   idx3 = (const int*)d_in[7];
    float* out = (float*)d_out;

    static bool attr_set = false;
    if (!attr_set) {
        cudaFuncSetAttribute(gemm_mma, cudaFuncAttributeMaxDynamicSharedMemorySize, SMEM_BYTES);
        attr_set = true;
    }

    transpose_W<<<dim3(KPAD / 32, C / 32), dim3(32, 8)>>>(W1, W2, W3);
    gemm_mma<<<dim3(BATCH / TM, SPLITK), NT, SMEM_BYTES>>>(x, idx1, idx2, idx3);

    int n4 = BATCH * C / 4;
    reduce_out<<<(n4 + 255) / 256, 256>>>(bias, out);
}

// round 5
// speedup vs baseline: 3.9039x; 1.8580x over previous
#include <cuda_runtime.h>
#include <cuda_fp16.h>
#include <cstdint>

#define BATCH 4096
#define F 32
#define C 128
#define K1 32
#define K2 496
#define K3 4960
#define KTOT 5488
#define KPADH 5504              // 172 * 32
#define KB 32                   // k per chunk = 2 fp16 mma k-steps of 16
#define NCH (KPADH / KB)        // 172
#define SPLITK 4
#define NCH_S (NCH / SPLITK)    // 43
#define TM 128
#define NT 256

// ---- smem byte layout ----
// A buffers: 16 fragment-blocks of 528B (132 words: 512B data + 16B pad)
#define ABLK_BYTES 528
#define ABUF_BYTES (16 * ABLK_BYTES)     // 8448
// W buffers: 128 rows x 96B (64B data + 32B pad, kills LDS.64 conflicts)
#define WROW_BYTES 96
#define WBUF_BYTES (128 * WROW_BYTES)    // 12288
#define SM_A0 0
#define SM_A1 ABUF_BYTES
#define SM_W0 (2 * ABUF_BYTES)
#define SM_W1 (2 * ABUF_BYTES + WBUF_BYTES)
#define SM_XS (2 * ABUF_BYTES + 2 * WBUF_BYTES)   // 41472
#define SMEM_BYTES (SM_XS + 128 * 33 * 4)         // 58368

__device__ __half g_Wt[(size_t)C * KPADH];            // W^T, half, pair-permuted k
__device__ float g_scratch[(size_t)SPLITK * BATCH * C];

__device__ __forceinline__ uint32_t smem_u32(const void* p) {
    return (uint32_t)__cvta_generic_to_shared(p);
}

__device__ __forceinline__ void mma_f16(float* c, const uint32_t* a, uint32_t b0, uint32_t b1) {
    asm volatile(
        "mma.sync.aligned.m16n8k16.row.col.f32.f16.f16.f32 "
        "{%0,%1,%2,%3}, {%4,%5,%6,%7}, {%8,%9}, {%0,%1,%2,%3};"
        : "+f"(c[0]), "+f"(c[1]), "+f"(c[2]), "+f"(c[3])
        : "r"(a[0]), "r"(a[1]), "r"(a[2]), "r"(a[3]), "r"(b0), "r"(b1));
}

__device__ __forceinline__ void cp16(uint32_t dst, const void* src) {
    asm volatile("cp.async.cg.shared.global [%0], [%1], 16;" :: "r"(dst), "l"(src) : "memory");
}

// pair-permutation of k within a 16-k block: [2t,2t+1,8+2t,9+2t] at half-offset 4t
__host__ __device__ __forceinline__ int kperm(int k) {   // k in [0,32)
    int ks = k >> 4, r = k & 15;
    return ks * 16 + ((r & 7) >> 1) * 4 + ((r >> 3) & 1) * 2 + (r & 1);
}

// ---------------- kernel 1: W -> g_Wt[c][perm(k)], half ----------------
__global__ void transpose_W(const float* __restrict__ W1,
                            const float* __restrict__ W2,
                            const float* __restrict__ W3)
{
    __shared__ float t[32][33];
    const int kt = blockIdx.x * 32, ct = blockIdx.y * 32;
    const int tx = threadIdx.x, ty = threadIdx.y;   // 32 x 8
#pragma unroll
    for (int j = 0; j < 32; j += 8) {
        int k = kt + ty + j;
        float v = 0.0f;
        if (k < KTOT) {
            const float* p;
            if (k < K1)            p = W1 + (size_t)k * C;
            else if (k < K1 + K2)  p = W2 + (size_t)(k - K1) * C;
            else                   p = W3 + (size_t)(k - (K1 + K2)) * C;
            v = p[ct + tx];
        }
        t[ty + j][tx] = v;
    }
    __syncthreads();
#pragma unroll
    for (int j = 0; j < 32; j += 8) {
        int c = ct + ty + j;
        g_Wt[(size_t)c * KPADH + kt + kperm(tx)] = __float2half_rn(t[tx][ty + j]);
    }
}

// ---------------- kernel 2: fp16 warp-mma GEMM, P on the fly ----------------
__global__ void __launch_bounds__(NT, 1) gemm_mma(
    const float* __restrict__ x,
    const int* __restrict__ idx1, const int* __restrict__ idx2, const int* __restrict__ idx3)
{
    extern __shared__ char smem[];
    float* xs = (float*)(smem + SM_XS);            // [128][33], col 32 = 1.0f

    const int tid  = threadIdx.x;
    const int b0   = blockIdx.x * TM;
    const int s    = blockIdx.y;
    const int lane = tid & 31;
    const int wid  = tid >> 5;
    const int gid  = lane >> 2;
    const int tg   = lane & 3;
    const int wm   = wid >> 1;    // 0..3 -> rows wm*32
    const int wn   = wid & 1;     // 0..1 -> cols wn*64

    // ---- x tile + ones column ----
    for (int t = tid; t < TM * (F / 4); t += NT) {
        int r = t >> 3, c4 = t & 7;
        float4 v = reinterpret_cast<const float4*>(x + (size_t)(b0 + r) * F)[c4];
        xs[r * 33 + c4 * 4 + 0] = v.x;
        xs[r * 33 + c4 * 4 + 1] = v.y;
        xs[r * 33 + c4 * 4 + 2] = v.z;
        xs[r * 33 + c4 * 4 + 3] = v.w;
    }
    if (tid < TM) xs[tid * 33 + F] = 1.0f;

    // staging roles: thread = (k-pair kp, row-group r8)
    const int kp = tid & 15;            // k pair: halves 2kp, 2kp+1 of chunk
    const int r8 = tid >> 4;            // rows r8*8 .. r8*8+7
    // fixed A-staging word offset pieces
    const int a_base_off = ((r8 >> 1) * 2 + (kp >> 3)) * 132   // block
                         + (kp & 3) * 4 + (r8 & 1) + 2 * ((kp >> 2) & 1);

    __half2 pv[8];

    auto cp_W = [&](int c, uint32_t wbuf) {
        const int kbase = (s * NCH_S + c) * KB;
        const __half* src0 = g_Wt + kbase;
#pragma unroll
        for (int q = 0; q < 2; ++q) {
            int flat = tid + q * NT;
            int n = flat >> 2, i = flat & 3;
            cp16(wbuf + n * WROW_BYTES + i * 16, src0 + (size_t)n * KPADH + i * 8);
        }
        asm volatile("cp.async.commit_group;" ::: "memory");
    };

    auto products = [&](int c) {
        const int kbase = (s * NCH_S + c) * KB;
        int kg0 = kbase + 2 * kp;
        int a0 = F, a1 = F, a2 = F, b0i = F, b1i = F, b2i = F;
        if (kg0 < K1)            { a0 = idx1[kg0]; }
        else if (kg0 < K1 + K2)  { const int* ip = idx2 + (size_t)(kg0 - K1) * 2;
                                   a0 = ip[0]; a1 = ip[1]; }
        else if (kg0 < KTOT)     { const int* ip = idx3 + (size_t)(kg0 - (K1 + K2)) * 3;
                                   a0 = ip[0]; a1 = ip[1]; a2 = ip[2]; }
        int kg1 = kg0 + 1;
        if (kg1 < K1)            { b0i = idx1[kg1]; }
        else if (kg1 < K1 + K2)  { const int* ip = idx2 + (size_t)(kg1 - K1) * 2;
                                   b0i = ip[0]; b1i = ip[1]; }
        else if (kg1 < KTOT)     { const int* ip = idx3 + (size_t)(kg1 - (K1 + K2)) * 3;
                                   b0i = ip[0]; b1i = ip[1]; b2i = ip[2]; }
        // dead k (>= KTOT): value irrelevant, W rows are zero
#pragma unroll
        for (int j = 0; j < 8; ++j) {
            const float* row = xs + (r8 * 8 + j) * 33;
            float p0 = row[a0] * row[a1] * row[a2];
            float p1 = row[b0i] * row[b1i] * row[b2i];
            pv[j] = __floats2half2_rn(p0, p1);
        }
    };

    auto sts_products = [&](uint32_t abuf) {
        uint32_t* Ab = (uint32_t*)(smem + 0) + 0;  // placeholder, use byte addressing
#pragma unroll
        for (int j = 0; j < 8; ++j) {
            *reinterpret_cast<__half2*>(smem + (abuf + (uint32_t)(a_base_off + 16 * j) * 4)) = pv[j];
        }
        (void)Ab;
    };

    float acc[2][8][4];
#pragma unroll
    for (int mb = 0; mb < 2; ++mb)
#pragma unroll
        for (int nb = 0; nb < 8; ++nb)
#pragma unroll
            for (int q = 0; q < 4; ++q) acc[mb][nb][q] = 0.0f;

    const uint32_t wsm[2] = { smem_u32(smem + SM_W0), smem_u32(smem + SM_W1) };
    const uint32_t asmb[2] = { SM_A0, SM_A1 };

    __syncthreads();                // xs ready (products read xs)

    // prologue: stage chunk 0 into buffer 0
    cp_W(0, wsm[0]);
    products(0);
    sts_products(asmb[0]);
    asm volatile("cp.async.wait_group 0;" ::: "memory");
    __syncthreads();

    for (int c = 0; c < NCH_S; ++c) {
        const int cur = c & 1;
        const int nxt = cur ^ 1;

        if (c + 1 < NCH_S) {
            cp_W(c + 1, wsm[nxt]);
            products(c + 1);
        }

        // ---- mma over buffer cur ----
        const char* Abuf = smem + asmb[cur];
        const char* Wbuf = smem + (cur ? SM_W1 : SM_W0);
#pragma unroll
        for (int ks = 0; ks < 2; ++ks) {
            uint32_t A[2][4];
#pragma unroll
            for (int mb = 0; mb < 2; ++mb) {
                uint4 v = *reinterpret_cast<const uint4*>(
                    Abuf + ((wm * 2 + mb) * 2 + ks) * ABLK_BYTES + lane * 16);
                A[mb][0] = v.x; A[mb][1] = v.y; A[mb][2] = v.z; A[mb][3] = v.w;
            }
#pragma unroll
            for (int nb = 0; nb < 8; ++nb) {
                uint2 b = *reinterpret_cast<const uint2*>(
                    Wbuf + (wn * 64 + nb * 8 + gid) * WROW_BYTES + ks * 32 + tg * 8);
                mma_f16(acc[0][nb], A[0], b.x, b.y);
                mma_f16(acc[1][nb], A[1], b.x, b.y);
            }
        }

        if (c + 1 < NCH_S) {
            sts_products(asmb[nxt]);
            asm volatile("cp.async.wait_group 0;" ::: "memory");
        }
        __syncthreads();
    }

    // ---- epilogue: deterministic split-K partials ----
    float* dst = g_scratch + ((size_t)s * BATCH + b0) * C;
#pragma unroll
    for (int mb = 0; mb < 2; ++mb) {
        int r = wm * 32 + mb * 16 + gid;
#pragma unroll
        for (int nb = 0; nb < 8; ++nb) {
            int col = wn * 64 + nb * 8 + 2 * tg;
            *reinterpret_cast<float2*>(dst + (size_t)r * C + col) =
                make_float2(acc[mb][nb][0], acc[mb][nb][1]);
            *reinterpret_cast<float2*>(dst + (size_t)(r + 8) * C + col) =
                make_float2(acc[mb][nb][2], acc[mb][nb][3]);
        }
    }
}

// ---------------- kernel 3: split-K reduce + bias ----------------
__global__ void reduce_out(const float* __restrict__ bias, float* __restrict__ out)
{
    int i = blockIdx.x * blockDim.x + threadIdx.x;
    const int n4 = BATCH * C / 4;
    if (i < n4) {
        float4 b = reinterpret_cast<const float4*>(bias)[i & (C / 4 - 1)];
        float sx = b.x, sy = b.y, sz = b.z, sw = b.w;
#pragma unroll
        for (int s = 0; s < SPLITK; s++) {
            float4 a = reinterpret_cast<const float4*>(g_scratch + (size_t)s * BATCH * C)[i];
            sx += a.x; sy += a.y; sz += a.z; sw += a.w;
        }
        reinterpret_cast<float4*>(out)[i] = make_float4(sx, sy, sz, sw);
    }
}

extern "C" void kernel_launch(void* const* d_in, const int* in_sizes, int n_in,
                              void* d_out, int out_size)
{
    const float* x    = (const float*)d_in[0];
    const float* bias = (const float*)d_in[1];
    const float* W1   = (const float*)d_in[2];
    const float* W2   = (const float*)d_in[3];
    const float* W3   = (const float*)d_in[4];
    const int*   idx1 = (const int*)d_in[5];
    const int*   idx2 = (const int*)d_in[6];
    const int*   idx3 = (const int*)d_in[7];
    float* out = (float*)d_out;

    static bool attr_set = false;
    if (!attr_set) {
        cudaFuncSetAttribute(gemm_mma, cudaFuncAttributeMaxDynamicSharedMemorySize, SMEM_BYTES);
        attr_set = true;
    }

    transpose_W<<<dim3(KPADH / 32, C / 32), dim3(32, 8)>>>(W1, W2, W3);
    gemm_mma<<<dim3(BATCH / TM, SPLITK), NT, SMEM_BYTES>>>(x, idx1, idx2, idx3);

    int n4 = BATCH * C / 4;
    reduce_out<<<(n4 + 255) / 256, 256>>>(bias, out);
}

// round 7
// speedup vs baseline: 4.3292x; 1.1089x over previous
#include <cuda_runtime.h>
#include <cuda_fp16.h>
#include <cstdint>

#define BATCH 4096
#define F 32
#define C 128
#define K1 32
#define K2 496
#define K3 4960
#define KTOT 5488
#define KPADH 5504              // 172 * 32
#define KB 32                   // k per chunk = 2 fp16 mma k-steps of 16
#define NCH (KPADH / KB)        // 172
#define SPLITK 4
#define NCH_S (NCH / SPLITK)    // 43
#define TM 128
#define NT 256

// ---- smem byte layout ----
#define ABLK_BYTES 528                    // 512B fragment block + 16B pad
#define ABUF_BYTES (16 * ABLK_BYTES)      // 8448
#define WROW_BYTES 96                     // 64B data + 32B pad
#define WBUF_BYTES (128 * WROW_BYTES)     // 12288
#define SM_A0  0
#define SM_A1  ABUF_BYTES                 // 8448
#define SM_W0  (2 * ABUF_BYTES)           // 16896
#define SM_W1  (SM_W0 + WBUF_BYTES)       // 29184
#define SM_W2  (SM_W1 + WBUF_BYTES)       // 41472
#define SM_XS  (SM_W2 + WBUF_BYTES)       // 53760
#define SM_IDX (SM_XS + 128 * 33 * 4)     // 70656
#define SMEM_BYTES (SM_IDX + NCH_S * KB * 4)   // 76160

__device__ __half g_Wt[(size_t)C * KPADH];            // W^T, half, pair-permuted k
__device__ float g_scratch[(size_t)SPLITK * BATCH * C];

__device__ __forceinline__ uint32_t smem_u32(const void* p) {
    return (uint32_t)__cvta_generic_to_shared(p);
}

__device__ __forceinline__ void mma_f16(float* c, const uint32_t* a, uint32_t b0, uint32_t b1) {
    asm volatile(
        "mma.sync.aligned.m16n8k16.row.col.f32.f16.f16.f32 "
        "{%0,%1,%2,%3}, {%4,%5,%6,%7}, {%8,%9}, {%0,%1,%2,%3};"
        : "+f"(c[0]), "+f"(c[1]), "+f"(c[2]), "+f"(c[3])
        : "r"(a[0]), "r"(a[1]), "r"(a[2]), "r"(a[3]), "r"(b0), "r"(b1));
}

__device__ __forceinline__ void cp16(uint32_t dst, const void* src) {
    asm volatile("cp.async.cg.shared.global [%0], [%1], 16;" :: "r"(dst), "l"(src) : "memory");
}

// pair-permutation of k within a 16-k block: [2t,2t+1,8+2t,9+2t] at half-offset 4t
__host__ __device__ __forceinline__ int kperm(int k) {   // k in [0,32)
    int ks = k >> 4, r = k & 15;
    return ks * 16 + ((r & 7) >> 1) * 4 + ((r >> 3) & 1) * 2 + (r & 1);
}

// ---------------- kernel 1: W -> g_Wt[c][perm(k)], half ----------------
__global__ void transpose_W(const float* __restrict__ W1,
                            const float* __restrict__ W2,
                            const float* __restrict__ W3)
{
    __shared__ float t[32][33];
    const int kt = blockIdx.x * 32;
    const int tx = threadIdx.x, ty = threadIdx.y;   // 32 x 8

    for (int ct = 0; ct < C; ct += 32) {
#pragma unroll
        for (int j = 0; j < 32; j += 8) {
            int k = kt + ty + j;
            float v = 0.0f;
            if (k < KTOT) {
                const float* p;
                if (k < K1)            p = W1 + (size_t)k * C;
                else if (k < K1 + K2)  p = W2 + (size_t)(k - K1) * C;
                else                   p = W3 + (size_t)(k - (K1 + K2)) * C;
                v = p[ct + tx];
            }
            t[ty + j][tx] = v;
        }
        __syncthreads();
#pragma unroll
        for (int j = 0; j < 32; j += 8) {
            int c = ct + ty + j;
            g_Wt[(size_t)c * KPADH + kt + kperm(tx)] = __float2half_rn(t[tx][ty + j]);
        }
        __syncthreads();
    }
}

// ---------------- kernel 2: fp16 warp-mma GEMM, P on the fly ----------------
__global__ void __launch_bounds__(NT, 1) gemm_mma(
    const float* __restrict__ x,
    const int* __restrict__ idx1, const int* __restrict__ idx2, const int* __restrict__ idx3)
{
    extern __shared__ char smem[];
    float*    xs   = (float*)(smem + SM_XS);       // [128][33], col 32 = 1.0f
    uint32_t* idxs = (uint32_t*)(smem + SM_IDX);   // packed (4*i0)|(4*i1)<<8|(4*i2)<<16

    const int tid  = threadIdx.x;
    const int b0   = blockIdx.x * TM;
    const int s    = blockIdx.y;
    const int lane = tid & 31;
    const int wid  = tid >> 5;
    const int gid  = lane >> 2;
    const int tg   = lane & 3;
    const int wm   = wid >> 1;    // 0..3 -> rows wm*32
    const int wn   = wid & 1;     // 0..1 -> cols wn*64

    // ---- x tile + ones column ----
    for (int t = tid; t < TM * (F / 4); t += NT) {
        int r = t >> 3, c4 = t & 7;
        float4 v = reinterpret_cast<const float4*>(x + (size_t)(b0 + r) * F)[c4];
        xs[r * 33 + c4 * 4 + 0] = v.x;
        xs[r * 33 + c4 * 4 + 1] = v.y;
        xs[r * 33 + c4 * 4 + 2] = v.z;
        xs[r * 33 + c4 * 4 + 3] = v.w;
    }
    if (tid < TM) xs[tid * 33 + F] = 1.0f;

    // ---- packed index table for this split (built once) ----
    for (int e = tid; e < NCH_S * KB; e += NT) {
        int kg = s * NCH_S * KB + e;
        int i0 = F, i1 = F, i2 = F;
        if (kg < K1)            { i0 = idx1[kg]; }
        else if (kg < K1 + K2)  { const int* ip = idx2 + (size_t)(kg - K1) * 2;
                                  i0 = ip[0]; i1 = ip[1]; }
        else if (kg < KTOT)     { const int* ip = idx3 + (size_t)(kg - (K1 + K2)) * 3;
                                  i0 = ip[0]; i1 = ip[1]; i2 = ip[2]; }
        idxs[e] = (uint32_t)i0 | ((uint32_t)i1 << 8) | ((uint32_t)i2 << 16);
    }

    // staging roles: thread = (k-pair kp, row-group r8)
    const int kp = tid & 15;            // k pair: halves 2kp, 2kp+1 of chunk
    const int r8 = tid >> 4;            // rows r8*8 .. r8*8+7
    const int a_base_off = ((r8 >> 1) * 2 + (kp >> 3)) * 132
                         + (kp & 3) * 4 + (r8 & 1) + 2 * ((kp >> 2) & 1);

    __half2 pv[8];

    const uint32_t wsm[3] = { smem_u32(smem + SM_W0), smem_u32(smem + SM_W1),
                              smem_u32(smem + SM_W2) };
    const uint32_t asmb[2] = { SM_A0, SM_A1 };

    auto cp_W = [&](int c, uint32_t wbuf) {
        const int kbase = (s * NCH_S + c) * KB;
        const __half* src0 = g_Wt + kbase;
#pragma unroll
        for (int q = 0; q < 2; ++q) {
            int flat = tid + q * NT;
            int n = flat >> 2, i = flat & 3;
            cp16(wbuf + n * WROW_BYTES + i * 16, src0 + (size_t)n * KPADH + i * 8);
        }
    };

    auto products = [&](int c) {
        uint32_t u0 = idxs[c * KB + 2 * kp];
        uint32_t u1 = idxs[c * KB + 2 * kp + 1];
        int a0 = u0 & 255, a1 = (u0 >> 8) & 255, a2 = (u0 >> 16) & 255;
        int c0 = u1 & 255, c1 = (u1 >> 8) & 255, c2 = (u1 >> 16) & 255;
#pragma unroll
        for (int j = 0; j < 8; ++j) {
            const float* row = xs + (r8 * 8 + j) * 33;
            float p0 = row[a0] * row[a1] * row[a2];
            float p1 = row[c0] * row[c1] * row[c2];
            pv[j] = __floats2half2_rn(p0, p1);
        }
    };

    auto sts_products = [&](uint32_t abuf) {
#pragma unroll
        for (int j = 0; j < 8; ++j)
            *reinterpret_cast<__half2*>(smem + abuf + (uint32_t)(a_base_off + 16 * j) * 4) = pv[j];
    };

    float acc[2][8][4];
#pragma unroll
    for (int mb = 0; mb < 2; ++mb)
#pragma unroll
        for (int nb = 0; nb < 8; ++nb)
#pragma unroll
            for (int q = 0; q < 4; ++q) acc[mb][nb][q] = 0.0f;

    __syncthreads();                // xs + idx table ready

    // prologue: W for chunks 0 and 1 in flight; A for chunk 0 staged
    cp_W(0, wsm[0]);
    asm volatile("cp.async.commit_group;" ::: "memory");
    cp_W(1, wsm[1]);
    asm volatile("cp.async.commit_group;" ::: "memory");
    products(0);
    sts_products(asmb[0]);
    asm volatile("cp.async.wait_group 1;" ::: "memory");   // W0 ready
    __syncthreads();

    for (int c = 0; c < NCH_S; ++c) {
        // keep 2 W groups in flight (empty group when past the end keeps counts aligned)
        if (c + 2 < NCH_S) cp_W(c + 2, wsm[(c + 2) % 3]);
        asm volatile("cp.async.commit_group;" ::: "memory");

        if (c + 1 < NCH_S) products(c + 1);

        // ---- mma over chunk c ----
        const char* Abuf = smem + asmb[c & 1];
        const char* Wbuf = smem + SM_W0 + (c % 3) * WBUF_BYTES;
#pragma unroll
        for (int ks = 0; ks < 2; ++ks) {
            uint32_t A[2][4];
#pragma unroll
            for (int mb = 0; mb < 2; ++mb) {
                uint4 v = *reinterpret_cast<const uint4*>(
                    Abuf + ((wm * 2 + mb) * 2 + ks) * ABLK_BYTES + lane * 16);
                A[mb][0] = v.x; A[mb][1] = v.y; A[mb][2] = v.z; A[mb][3] = v.w;
            }
#pragma unroll
            for (int nb = 0; nb < 8; ++nb) {
                uint2 b = *reinterpret_cast<const uint2*>(
                    Wbuf + (wn * 64 + nb * 8 + gid) * WROW_BYTES + ks * 32 + tg * 8);
                mma_f16(acc[0][nb], A[0], b.x, b.y);
                mma_f16(acc[1][nb], A[1], b.x, b.y);
            }
        }

        if (c + 1 < NCH_S) sts_products(asmb[(c + 1) & 1]);
        asm volatile("cp.async.wait_group 1;" ::: "memory");   // W(c+1) ready
        __syncthreads();
    }

    // ---- epilogue: deterministic split-K partials ----
    float* dst = g_scratch + ((size_t)s * BATCH + b0) * C;
#pragma unroll
    for (int mb = 0; mb < 2; ++mb) {
        int r = wm * 32 + mb * 16 + gid;
#pragma unroll
        for (int nb = 0; nb < 8; ++nb) {
            int col = wn * 64 + nb * 8 + 2 * tg;
            *reinterpret_cast<float2*>(dst + (size_t)r * C + col) =
                make_float2(acc[mb][nb][0], acc[mb][nb][1]);
            *reinterpret_cast<float2*>(dst + (size_t)(r + 8) * C + col) =
                make_float2(acc[mb][nb][2], acc[mb][nb][3]);
        }
    }
}

// ---------------- kernel 3: split-K reduce + bias ----------------
__global__ void reduce_out(const float* __restrict__ bias, float* __restrict__ out)
{
    const int n4 = BATCH * C / 4;
    int base = blockIdx.x * blockDim.x * 2 + threadIdx.x;
#pragma unroll
    for (int t = 0; t < 2; ++t) {
        int i = base + t * blockDim.x;
        if (i < n4) {
            float4 b = reinterpret_cast<const float4*>(bias)[i & (C / 4 - 1)];
            float sx = b.x, sy = b.y, sz = b.z, sw = b.w;
#pragma unroll
            for (int s = 0; s < SPLITK; s++) {
                float4 a = reinterpret_cast<const float4*>(g_scratch + (size_t)s * BATCH * C)[i];
                sx += a.x; sy += a.y; sz += a.z; sw += a.w;
            }
            reinterpret_cast<float4*>(out)[i] = make_float4(sx, sy, sz, sw);
        }
    }
}

extern "C" void kernel_launch(void* const* d_in, const int* in_sizes, int n_in,
                              void* d_out, int out_size)
{
    const float* x    = (const float*)d_in[0];
    const float* bias = (const float*)d_in[1];
    const float* W1   = (const float*)d_in[2];
    const float* W2   = (const float*)d_in[3];
    const float* W3   = (const float*)d_in[4];
    const int*   idx1 = (const int*)d_in[5];
    const int*   idx2 = (const int*)d_in[6];
    const int*   idx3 = (const int*)d_in[7];
    float* out = (float*)d_out;

    static bool attr_set = false;
    if (!attr_set) {
        cudaFuncSetAttribute(gemm_mma, cudaFuncAttributeMaxDynamicSharedMemorySize, SMEM_BYTES);
        attr_set = true;
    }

    transpose_W<<<dim3(KPADH / 32, 1), dim3(32, 8)>>>(W1, W2, W3);
    gemm_mma<<<dim3(BATCH / TM, SPLITK), NT, SMEM_BYTES>>>(x, idx1, idx2, idx3);

    int n4 = BATCH * C / 4;
    reduce_out<<<(n4 + 511) / 512, 256>>>(bias, out);
}

// round 8
// speedup vs baseline: 5.3489x; 1.2356x over previous
#include <cuda_runtime.h>
#include <cuda_fp16.h>
#include <cstdint>

#define BATCH 4096
#define F 32
#define C 128
#define K1 32
#define K2 496
#define K3 4960
#define KTOT 5488
#define KPADH 5760              // 180 * 32, divisible by SPLITK*KB
#define KB 32                   // k per chunk = 2 fp16 mma k-steps of 16
#define NCH (KPADH / KB)        // 180
#define SPLITK 9
#define NCH_S (NCH / SPLITK)    // 20
#define TM 128
#define NT 256

// ---- smem byte layout ----
#define ABLK_BYTES 528                    // 512B fragment block + 16B pad
#define ABUF_BYTES (16 * ABLK_BYTES)      // 8448
#define WROW_BYTES 96                     // 64B data + 32B pad
#define WBUF_BYTES (128 * WROW_BYTES)     // 12288
#define SM_A0  0
#define SM_A1  ABUF_BYTES                 // 8448
#define SM_W0  (2 * ABUF_BYTES)           // 16896
#define SM_W1  (SM_W0 + WBUF_BYTES)       // 29184
#define SM_W2  (SM_W1 + WBUF_BYTES)       // 41472
#define SM_XS  (SM_W2 + WBUF_BYTES)       // 53760
#define SM_IDX (SM_XS + 128 * 33 * 4)     // 70656
#define SMEM_BYTES (SM_IDX + NCH_S * KB * 4)   // 73216  -> 2 CTAs/SM

__device__ __half g_Wt[(size_t)C * KPADH];            // W^T, half, pair-permuted k
__device__ float g_scratch[(size_t)SPLITK * BATCH * C];

__device__ __forceinline__ uint32_t smem_u32(const void* p) {
    return (uint32_t)__cvta_generic_to_shared(p);
}

__device__ __forceinline__ void mma_f16(float* c, const uint32_t* a, uint32_t b0, uint32_t b1) {
    asm volatile(
        "mma.sync.aligned.m16n8k16.row.col.f32.f16.f16.f32 "
        "{%0,%1,%2,%3}, {%4,%5,%6,%7}, {%8,%9}, {%0,%1,%2,%3};"
        : "+f"(c[0]), "+f"(c[1]), "+f"(c[2]), "+f"(c[3])
        : "r"(a[0]), "r"(a[1]), "r"(a[2]), "r"(a[3]), "r"(b0), "r"(b1));
}

__device__ __forceinline__ void cp16(uint32_t dst, const void* src) {
    asm volatile("cp.async.cg.shared.global [%0], [%1], 16;" :: "r"(dst), "l"(src) : "memory");
}

// position p in a 16-k block -> source k offset (inverse of the pair-permutation)
__device__ __forceinline__ int ksrc(int p) {   // p in [0,16)
    return (((p >> 1) & 1) << 3) + ((p >> 2) << 1) + (p & 1);
}

// ---------------- kernel 1: W -> g_Wt[c][perm(k)], half (single-pass, high MLP) ----------------
__global__ void transpose_W(const float* __restrict__ W1,
                            const float* __restrict__ W2,
                            const float* __restrict__ W3)
{
    __shared__ float t[32][65];               // 32 k-rows x 64 c-cols
    const int kt = blockIdx.x * 32;           // k tile
    const int ct = blockIdx.y * 64;           // c tile
    const int tid = threadIdx.x;              // 256

    // load: 32 rows x 16 float4, 2 per thread, coalesced; zero-pad dead k
#pragma unroll
    for (int q = 0; q < 2; ++q) {
        int row = tid >> 3;
        int c4  = (tid & 7) + q * 8;
        int k   = kt + row;
        float4 v = make_float4(0.f, 0.f, 0.f, 0.f);
        if (k < KTOT) {
            const float* p;
            if (k < K1)            p = W1 + (size_t)k * C;
            else if (k < K1 + K2)  p = W2 + (size_t)(k - K1) * C;
            else                   p = W3 + (size_t)(k - (K1 + K2)) * C;
            v = *reinterpret_cast<const float4*>(p + ct + c4 * 4);
        }
        t[row][c4 * 4 + 0] = v.x;
        t[row][c4 * 4 + 1] = v.y;
        t[row][c4 * 4 + 2] = v.z;
        t[row][c4 * 4 + 3] = v.w;
    }
    __syncthreads();

    // write: threads 0..127, each one (c, 16k-block): 16 halves = one 32B sector
    if (tid < 128) {
        const int c  = tid & 63;
        const int kb = tid >> 6;
        __half2 h2[8];
#pragma unroll
        for (int p2 = 0; p2 < 8; ++p2) {
            float a = t[kb * 16 + ksrc(2 * p2)][c];
            float b = t[kb * 16 + ksrc(2 * p2 + 1)][c];
            h2[p2] = __floats2half2_rn(a, b);
        }
        __half* dst = g_Wt + (size_t)(ct + c) * KPADH + kt + kb * 16;
        reinterpret_cast<uint4*>(dst)[0] = *reinterpret_cast<uint4*>(&h2[0]);
        reinterpret_cast<uint4*>(dst)[1] = *reinterpret_cast<uint4*>(&h2[4]);
    }
}

// ---------------- kernel 2: fp16 warp-mma GEMM, P on the fly ----------------
__global__ void __launch_bounds__(NT, 2) gemm_mma(
    const float* __restrict__ x,
    const int* __restrict__ idx1, const int* __restrict__ idx2, const int* __restrict__ idx3)
{
    extern __shared__ char smem[];
    float*    xs   = (float*)(smem + SM_XS);       // [128][33], col 32 = 1.0f
    uint32_t* idxs = (uint32_t*)(smem + SM_IDX);   // packed i0|i1<<8|i2<<16

    const int tid  = threadIdx.x;
    const int b0   = blockIdx.x * TM;
    const int s    = blockIdx.y;
    const int lane = tid & 31;
    const int wid  = tid >> 5;
    const int gid  = lane >> 2;
    const int tg   = lane & 3;
    const int wm   = wid >> 1;    // 0..3 -> rows wm*32
    const int wn   = wid & 1;     // 0..1 -> cols wn*64

    // ---- x tile + ones column ----
    for (int t = tid; t < TM * (F / 4); t += NT) {
        int r = t >> 3, c4 = t & 7;
        float4 v = reinterpret_cast<const float4*>(x + (size_t)(b0 + r) * F)[c4];
        xs[r * 33 + c4 * 4 + 0] = v.x;
        xs[r * 33 + c4 * 4 + 1] = v.y;
        xs[r * 33 + c4 * 4 + 2] = v.z;
        xs[r * 33 + c4 * 4 + 3] = v.w;
    }
    if (tid < TM) xs[tid * 33 + F] = 1.0f;

    // ---- packed index table for this split (built once) ----
    for (int e = tid; e < NCH_S * KB; e += NT) {
        int kg = s * NCH_S * KB + e;
        int i0 = F, i1 = F, i2 = F;
        if (kg < K1)            { i0 = idx1[kg]; }
        else if (kg < K1 + K2)  { const int* ip = idx2 + (size_t)(kg - K1) * 2;
                                  i0 = ip[0]; i1 = ip[1]; }
        else if (kg < KTOT)     { const int* ip = idx3 + (size_t)(kg - (K1 + K2)) * 3;
                                  i0 = ip[0]; i1 = ip[1]; i2 = ip[2]; }
        idxs[e] = (uint32_t)i0 | ((uint32_t)i1 << 8) | ((uint32_t)i2 << 16);
    }

    // staging roles: thread = (k-pair kp, row-group r8)
    const int kp = tid & 15;            // k pair: halves 2kp, 2kp+1 of chunk
    const int r8 = tid >> 4;            // rows r8*8 .. r8*8+7
    const int a_base_off = ((r8 >> 1) * 2 + (kp >> 3)) * 132
                         + (kp & 3) * 4 + (r8 & 1) + 2 * ((kp >> 2) & 1);

    __half2 pv[8];

    const uint32_t wsm[3] = { smem_u32(smem + SM_W0), smem_u32(smem + SM_W1),
                              smem_u32(smem + SM_W2) };
    const uint32_t asmb[2] = { SM_A0, SM_A1 };

    auto cp_W = [&](int c, uint32_t wbuf) {
        const int kbase = (s * NCH_S + c) * KB;
        const __half* src0 = g_Wt + kbase;
#pragma unroll
        for (int q = 0; q < 2; ++q) {
            int flat = tid + q * NT;
            int n = flat >> 2, i = flat & 3;
            cp16(wbuf + n * WROW_BYTES + i * 16, src0 + (size_t)n * KPADH + i * 8);
        }
    };

    auto products = [&](int c) {
        uint32_t u0 = idxs[c * KB + 2 * kp];
        uint32_t u1 = idxs[c * KB + 2 * kp + 1];
        int a0 = u0 & 255, a1 = (u0 >> 8) & 255, a2 = (u0 >> 16) & 255;
        int c0 = u1 & 255, c1 = (u1 >> 8) & 255, c2 = (u1 >> 16) & 255;
#pragma unroll
        for (int j = 0; j < 8; ++j) {
            const float* row = xs + (r8 * 8 + j) * 33;
            float p0 = row[a0] * row[a1] * row[a2];
            float p1 = row[c0] * row[c1] * row[c2];
            pv[j] = __floats2half2_rn(p0, p1);
        }
    };

    auto sts_products = [&](uint32_t abuf) {
#pragma unroll
        for (int j = 0; j < 8; ++j)
            *reinterpret_cast<__half2*>(smem + abuf + (uint32_t)(a_base_off + 16 * j) * 4) = pv[j];
    };

    float acc[2][8][4];
#pragma unroll
    for (int mb = 0; mb < 2; ++mb)
#pragma unroll
        for (int nb = 0; nb < 8; ++nb)
#pragma unroll
            for (int q = 0; q < 4; ++q) acc[mb][nb][q] = 0.0f;

    __syncthreads();                // xs + idx table ready

    // prologue: W for chunks 0 and 1 in flight; A for chunk 0 staged
    cp_W(0, wsm[0]);
    asm volatile("cp.async.commit_group;" ::: "memory");
    cp_W(1, wsm[1]);
    asm volatile("cp.async.commit_group;" ::: "memory");
    products(0);
    sts_products(asmb[0]);
    asm volatile("cp.async.wait_group 1;" ::: "memory");   // W0 ready
    __syncthreads();

    for (int c = 0; c < NCH_S; ++c) {
        if (c + 2 < NCH_S) cp_W(c + 2, wsm[(c + 2) % 3]);
        asm volatile("cp.async.commit_group;" ::: "memory");

        if (c + 1 < NCH_S) products(c + 1);

        // ---- mma over chunk c ----
        const char* Abuf = smem + asmb[c & 1];
        const char* Wbuf = smem + SM_W0 + (c % 3) * WBUF_BYTES;
#pragma unroll
        for (int ks = 0; ks < 2; ++ks) {
            uint32_t A[2][4];
#pragma unroll
            for (int mb = 0; mb < 2; ++mb) {
                uint4 v = *reinterpret_cast<const uint4*>(
                    Abuf + ((wm * 2 + mb) * 2 + ks) * ABLK_BYTES + lane * 16);
                A[mb][0] = v.x; A[mb][1] = v.y; A[mb][2] = v.z; A[mb][3] = v.w;
            }
#pragma unroll
            for (int nb = 0; nb < 8; ++nb) {
                uint2 b = *reinterpret_cast<const uint2*>(
                    Wbuf + (wn * 64 + nb * 8 + gid) * WROW_BYTES + ks * 32 + tg * 8);
                mma_f16(acc[0][nb], A[0], b.x, b.y);
                mma_f16(acc[1][nb], A[1], b.x, b.y);
            }
        }

        if (c + 1 < NCH_S) sts_products(asmb[(c + 1) & 1]);
        asm volatile("cp.async.wait_group 1;" ::: "memory");   // W(c+1) ready
        __syncthreads();
    }

    // ---- epilogue: deterministic split-K partials ----
    float* dst = g_scratch + ((size_t)s * BATCH + b0) * C;
#pragma unroll
    for (int mb = 0; mb < 2; ++mb) {
        int r = wm * 32 + mb * 16 + gid;
#pragma unroll
        for (int nb = 0; nb < 8; ++nb) {
            int col = wn * 64 + nb * 8 + 2 * tg;
            *reinterpret_cast<float2*>(dst + (size_t)r * C + col) =
                make_float2(acc[mb][nb][0], acc[mb][nb][1]);
            *reinterpret_cast<float2*>(dst + (size_t)(r + 8) * C + col) =
                make_float2(acc[mb][nb][2], acc[mb][nb][3]);
        }
    }
}

// ---------------- kernel 3: split-K reduce + bias ----------------
__global__ void reduce_out(const float* __restrict__ bias, float* __restrict__ out)
{
    const int n4 = BATCH * C / 4;
    int base = blockIdx.x * blockDim.x * 2 + threadIdx.x;
#pragma unroll
    for (int t = 0; t < 2; ++t) {
        int i = base + t * blockDim.x;
        if (i < n4) {
            float4 b = reinterpret_cast<const float4*>(bias)[i & (C / 4 - 1)];
            float sx = b.x, sy = b.y, sz = b.z, sw = b.w;
#pragma unroll
            for (int s = 0; s < SPLITK; s++) {
                float4 a = reinterpret_cast<const float4*>(g_scratch + (size_t)s * BATCH * C)[i];
                sx += a.x; sy += a.y; sz += a.z; sw += a.w;
            }
            reinterpret_cast<float4*>(out)[i] = make_float4(sx, sy, sz, sw);
        }
    }
}

extern "C" void kernel_launch(void* const* d_in, const int* in_sizes, int n_in,
                              void* d_out, int out_size)
{
    const float* x    = (const float*)d_in[0];
    const float* bias = (const float*)d_in[1];
    const float* W1   = (const float*)d_in[2];
    const float* W2   = (const float*)d_in[3];
    const float* W3   = (const float*)d_in[4];
    const int*   idx1 = (const int*)d_in[5];
    const int*   idx2 = (const int*)d_in[6];
    const int*   idx3 = (const int*)d_in[7];
    float* out = (float*)d_out;

    static bool attr_set = false;
    if (!attr_set) {
        cudaFuncSetAttribute(gemm_mma, cudaFuncAttributeMaxDynamicSharedMemorySize, SMEM_BYTES);
        attr_set = true;
    }

    transpose_W<<<dim3(KPADH / 32, C / 64), 256>>>(W1, W2, W3);
    gemm_mma<<<dim3(BATCH / TM, SPLITK), NT, SMEM_BYTES>>>(x, idx1, idx2, idx3);

    int n4 = BATCH * C / 4;
    reduce_out<<<(n4 + 511) / 512, 256>>>(bias, out);
}

// round 9
// speedup vs baseline: 5.7575x; 1.0764x over previous
#include <cuda_runtime.h>
#include <cuda_fp16.h>
#include <cstdint>

#define BATCH 4096
#define F 32
#define C 128
#define K1 32
#define K2 496
#define K3 4960
#define KTOT 5488
#define KPADH 5760              // 180 * 32, divisible by SPLITK*KB
#define KB 32                   // k per chunk = 2 fp16 mma k-steps of 16
#define NCH (KPADH / KB)        // 180
#define SPLITK 9
#define NCH_S (NCH / SPLITK)    // 20
#define TM 128
#define NT 256
#define XT_STRIDE 132           // floats; 16B-aligned feature rows, bank = (4f + r) & 31

// ---- smem byte layout ----
#define ABLK_BYTES 528                    // 512B fragment block + 16B pad
#define ABUF_BYTES (16 * ABLK_BYTES)      // 8448
#define WROW_BYTES 96                     // 64B data + 32B pad
#define WBUF_BYTES (128 * WROW_BYTES)     // 12288
#define SM_A0  0
#define SM_A1  ABUF_BYTES                 // 8448
#define SM_W0  (2 * ABUF_BYTES)           // 16896
#define SM_W1  (SM_W0 + WBUF_BYTES)       // 29184
#define SM_W2  (SM_W1 + WBUF_BYTES)       // 41472
#define SM_XS  (SM_W2 + WBUF_BYTES)       // 53760
#define SM_IDX (SM_XS + 33 * XT_STRIDE * 4)    // 71184
#define SMEM_BYTES (SM_IDX + NCH_S * KB * 4)   // 73744  -> 2 CTAs/SM

__device__ __half g_Wt[(size_t)C * KPADH];            // W^T, half, pair-permuted k
__device__ float g_scratch[(size_t)SPLITK * BATCH * C];

__device__ __forceinline__ uint32_t smem_u32(const void* p) {
    return (uint32_t)__cvta_generic_to_shared(p);
}

__device__ __forceinline__ void mma_f16(float* c, const uint32_t* a, uint32_t b0, uint32_t b1) {
    asm volatile(
        "mma.sync.aligned.m16n8k16.row.col.f32.f16.f16.f32 "
        "{%0,%1,%2,%3}, {%4,%5,%6,%7}, {%8,%9}, {%0,%1,%2,%3};"
        : "+f"(c[0]), "+f"(c[1]), "+f"(c[2]), "+f"(c[3])
        : "r"(a[0]), "r"(a[1]), "r"(a[2]), "r"(a[3]), "r"(b0), "r"(b1));
}

__device__ __forceinline__ void cp16(uint32_t dst, const void* src) {
    asm volatile("cp.async.cg.shared.global [%0], [%1], 16;" :: "r"(dst), "l"(src) : "memory");
}

// position p in a 16-k block -> source k offset (inverse of the pair-permutation)
__device__ __forceinline__ int ksrc(int p) {   // p in [0,16)
    return (((p >> 1) & 1) << 3) + ((p >> 2) << 1) + (p & 1);
}

// ---------------- kernel 1: W -> g_Wt[c][perm(k)], half (16k x 64c tiles) ----------------
__global__ void transpose_W(const float* __restrict__ W1,
                            const float* __restrict__ W2,
                            const float* __restrict__ W3)
{
    __shared__ float t[16][65];
    const int kt = blockIdx.x * 16;
    const int ct = blockIdx.y * 64;
    const int tid = threadIdx.x;              // 128

#pragma unroll
    for (int q = 0; q < 2; ++q) {
        int flat = tid + q * 128;
        int row = flat >> 4, c4 = flat & 15;
        int k = kt + row;
        float4 v = make_float4(0.f, 0.f, 0.f, 0.f);
        if (k < KTOT) {
            const float* p;
            if (k < K1)            p = W1 + (size_t)k * C;
            else if (k < K1 + K2)  p = W2 + (size_t)(k - K1) * C;
            else                   p = W3 + (size_t)(k - (K1 + K2)) * C;
            v = *reinterpret_cast<const float4*>(p + ct + c4 * 4);
        }
        t[row][c4 * 4 + 0] = v.x;
        t[row][c4 * 4 + 1] = v.y;
        t[row][c4 * 4 + 2] = v.z;
        t[row][c4 * 4 + 3] = v.w;
    }
    __syncthreads();

    // write: thread = (c 0..63, h 0..1): 8 permuted halves = 16B
    {
        const int c = tid & 63;
        const int h = tid >> 6;
        __half2 h2[4];
#pragma unroll
        for (int p2 = 0; p2 < 4; ++p2) {
            int pp = h * 8 + p2 * 2;
            float a = t[ksrc(pp)][c];
            float b = t[ksrc(pp + 1)][c];
            h2[p2] = __floats2half2_rn(a, b);
        }
        __half* dst = g_Wt + (size_t)(ct + c) * KPADH + kt + h * 8;
        *reinterpret_cast<uint4*>(dst) = *reinterpret_cast<uint4*>(h2);
    }
}

// ---------------- kernel 2: fp16 warp-mma GEMM, P on the fly ----------------
__global__ void __launch_bounds__(NT, 2) gemm_mma(
    const float* __restrict__ x,
    const int* __restrict__ idx1, const int* __restrict__ idx2, const int* __restrict__ idx3)
{
    extern __shared__ char smem[];
    float*    xs_t = (float*)(smem + SM_XS);       // [33][132]: xs_t[f][r]; f=32 -> ones
    uint32_t* idxs = (uint32_t*)(smem + SM_IDX);   // packed i0|i1<<8|i2<<16

    const int tid  = threadIdx.x;
    const int b0   = blockIdx.x * TM;
    const int s    = blockIdx.y;
    const int lane = tid & 31;
    const int wid  = tid >> 5;
    const int gid  = lane >> 2;
    const int tg   = lane & 3;
    const int wm   = wid >> 1;    // 0..3 -> rows wm*32
    const int wn   = wid & 1;     // 0..1 -> cols wn*64

    // ---- x tile, transposed: xs_t[f][r] = x[b0+r][f]; ones row at f=32 ----
    for (int t = tid; t < TM * (F / 4); t += NT) {
        int r = t >> 3, c4 = t & 7;
        float4 v = reinterpret_cast<const float4*>(x + (size_t)(b0 + r) * F)[c4];
        xs_t[(c4 * 4 + 0) * XT_STRIDE + r] = v.x;
        xs_t[(c4 * 4 + 1) * XT_STRIDE + r] = v.y;
        xs_t[(c4 * 4 + 2) * XT_STRIDE + r] = v.z;
        xs_t[(c4 * 4 + 3) * XT_STRIDE + r] = v.w;
    }
    if (tid < TM) xs_t[F * XT_STRIDE + tid] = 1.0f;

    // ---- packed index table for this split (built once) ----
    for (int e = tid; e < NCH_S * KB; e += NT) {
        int kg = s * NCH_S * KB + e;
        int i0 = F, i1 = F, i2 = F;
        if (kg < K1)            { i0 = idx1[kg]; }
        else if (kg < K1 + K2)  { const int* ip = idx2 + (size_t)(kg - K1) * 2;
                                  i0 = ip[0]; i1 = ip[1]; }
        else if (kg < KTOT)     { const int* ip = idx3 + (size_t)(kg - (K1 + K2)) * 3;
                                  i0 = ip[0]; i1 = ip[1]; i2 = ip[2]; }
        idxs[e] = (uint32_t)i0 | ((uint32_t)i1 << 8) | ((uint32_t)i2 << 16);
    }

    // staging roles: thread = (k-pair kp, row-group r8)
    const int kp = tid & 15;            // k pair: halves 2kp, 2kp+1 of chunk
    const int r8 = tid >> 4;            // rows r8*8 .. r8*8+7
    const int a_base_off = ((r8 >> 1) * 2 + (kp >> 3)) * 132
                         + (kp & 3) * 4 + (r8 & 1) + 2 * ((kp >> 2) & 1);

    __half2 pv[8];

    const uint32_t wsm[3] = { smem_u32(smem + SM_W0), smem_u32(smem + SM_W1),
                              smem_u32(smem + SM_W2) };
    const uint32_t asmb[2] = { SM_A0, SM_A1 };

    auto cp_W = [&](int c, uint32_t wbuf) {
        const int kbase = (s * NCH_S + c) * KB;
        const __half* src0 = g_Wt + kbase;
#pragma unroll
        for (int q = 0; q < 2; ++q) {
            int flat = tid + q * NT;
            int n = flat >> 2, i = flat & 3;
            cp16(wbuf + n * WROW_BYTES + i * 16, src0 + (size_t)n * KPADH + i * 8);
        }
    };

    auto products = [&](int c) {
        uint32_t u0 = idxs[c * KB + 2 * kp];
        uint32_t u1 = idxs[c * KB + 2 * kp + 1];
        const float* xa0 = xs_t + (u0 & 255) * XT_STRIDE + r8 * 8;
        const float* xa1 = xs_t + ((u0 >> 8) & 255) * XT_STRIDE + r8 * 8;
        const float* xa2 = xs_t + ((u0 >> 16) & 255) * XT_STRIDE + r8 * 8;
        const float* xb0 = xs_t + (u1 & 255) * XT_STRIDE + r8 * 8;
        const float* xb1 = xs_t + ((u1 >> 8) & 255) * XT_STRIDE + r8 * 8;
        const float* xb2 = xs_t + ((u1 >> 16) & 255) * XT_STRIDE + r8 * 8;
#pragma unroll
        for (int q = 0; q < 2; ++q) {
            float4 va0 = reinterpret_cast<const float4*>(xa0)[q];
            float4 va1 = reinterpret_cast<const float4*>(xa1)[q];
            float4 va2 = reinterpret_cast<const float4*>(xa2)[q];
            float4 vb0 = reinterpret_cast<const float4*>(xb0)[q];
            float4 vb1 = reinterpret_cast<const float4*>(xb1)[q];
            float4 vb2 = reinterpret_cast<const float4*>(xb2)[q];
            pv[q * 4 + 0] = __floats2half2_rn(va0.x * va1.x * va2.x, vb0.x * vb1.x * vb2.x);
            pv[q * 4 + 1] = __floats2half2_rn(va0.y * va1.y * va2.y, vb0.y * vb1.y * vb2.y);
            pv[q * 4 + 2] = __floats2half2_rn(va0.z * va1.z * va2.z, vb0.z * vb1.z * vb2.z);
            pv[q * 4 + 3] = __floats2half2_rn(va0.w * va1.w * va2.w, vb0.w * vb1.w * vb2.w);
        }
    };

    auto sts_products = [&](uint32_t abuf) {
#pragma unroll
        for (int j = 0; j < 8; ++j)
            *reinterpret_cast<__half2*>(smem + abuf + (uint32_t)(a_base_off + 16 * j) * 4) = pv[j];
    };

    float acc[2][8][4];
#pragma unroll
    for (int mb = 0; mb < 2; ++mb)
#pragma unroll
        for (int nb = 0; nb < 8; ++nb)
#pragma unroll
            for (int q = 0; q < 4; ++q) acc[mb][nb][q] = 0.0f;

    __syncthreads();                // xs_t + idx table ready

    // prologue: W for chunks 0 and 1 in flight; A for chunk 0 staged
    cp_W(0, wsm[0]);
    asm volatile("cp.async.commit_group;" ::: "memory");
    cp_W(1, wsm[1]);
    asm volatile("cp.async.commit_group;" ::: "memory");
    products(0);
    sts_products(asmb[0]);
    asm volatile("cp.async.wait_group 1;" ::: "memory");   // W0 ready
    __syncthreads();

    for (int c = 0; c < NCH_S; ++c) {
        if (c + 2 < NCH_S) cp_W(c + 2, wsm[(c + 2) % 3]);
        asm volatile("cp.async.commit_group;" ::: "memory");

        if (c + 1 < NCH_S) products(c + 1);

        // ---- mma over chunk c ----
        const char* Abuf = smem + asmb[c & 1];
        const char* Wbuf = smem + SM_W0 + (c % 3) * WBUF_BYTES;
#pragma unroll
        for (int ks = 0; ks < 2; ++ks) {
            uint32_t A[2][4];
#pragma unroll
            for (int mb = 0; mb < 2; ++mb) {
                uint4 v = *reinterpret_cast<const uint4*>(
                    Abuf + ((wm * 2 + mb) * 2 + ks) * ABLK_BYTES + lane * 16);
                A[mb][0] = v.x; A[mb][1] = v.y; A[mb][2] = v.z; A[mb][3] = v.w;
            }
#pragma unroll
            for (int nb = 0; nb < 8; ++nb) {
                uint2 b = *reinterpret_cast<const uint2*>(
                    Wbuf + (wn * 64 + nb * 8 + gid) * WROW_BYTES + ks * 32 + tg * 8);
                mma_f16(acc[0][nb], A[0], b.x, b.y);
                mma_f16(acc[1][nb], A[1], b.x, b.y);
            }
        }

        if (c + 1 < NCH_S) sts_products(asmb[(c + 1) & 1]);
        asm volatile("cp.async.wait_group 1;" ::: "memory");   // W(c+1) ready
        __syncthreads();
    }

    // ---- epilogue: deterministic split-K partials ----
    float* dst = g_scratch + ((size_t)s * BATCH + b0) * C;
#pragma unroll
    for (int mb = 0; mb < 2; ++mb) {
        int r = wm * 32 + mb * 16 + gid;
#pragma unroll
        for (int nb = 0; nb < 8; ++nb) {
            int col = wn * 64 + nb * 8 + 2 * tg;
            *reinterpret_cast<float2*>(dst + (size_t)r * C + col) =
                make_float2(acc[mb][nb][0], acc[mb][nb][1]);
            *reinterpret_cast<float2*>(dst + (size_t)(r + 8) * C + col) =
                make_float2(acc[mb][nb][2], acc[mb][nb][3]);
        }
    }
}

// ---------------- kernel 3: split-K reduce + bias ----------------
__global__ void reduce_out(const float* __restrict__ bias, float* __restrict__ out)
{
    const int n4 = BATCH * C / 4;
    int i = blockIdx.x * blockDim.x + threadIdx.x;
    if (i < n4) {
        float4 b = reinterpret_cast<const float4*>(bias)[i & (C / 4 - 1)];
        float sx = b.x, sy = b.y, sz = b.z, sw = b.w;
#pragma unroll
        for (int s = 0; s < SPLITK; s++) {
            float4 a = reinterpret_cast<const float4*>(g_scratch + (size_t)s * BATCH * C)[i];
            sx += a.x; sy += a.y; sz += a.z; sw += a.w;
        }
        reinterpret_cast<float4*>(out)[i] = make_float4(sx, sy, sz, sw);
    }
}

extern "C" void kernel_launch(void* const* d_in, const int* in_sizes, int n_in,
                              void* d_out, int out_size)
{
    const float* x    = (const float*)d_in[0];
    const float* bias = (const float*)d_in[1];
    const float* W1   = (const float*)d_in[2];
    const float* W2   = (const float*)d_in[3];
    const float* W3   = (const float*)d_in[4];
    const int*   idx1 = (const int*)d_in[5];
    const int*   idx2 = (const int*)d_in[6];
    const int*   idx3 = (const int*)d_in[7];
    float* out = (float*)d_out;

    static bool attr_set = false;
    if (!attr_set) {
        cudaFuncSetAttribute(gemm_mma, cudaFuncAttributeMaxDynamicSharedMemorySize, SMEM_BYTES);
        attr_set = true;
    }

    transpose_W<<<dim3(KPADH / 16, C / 64), 128>>>(W1, W2, W3);
    gemm_mma<<<dim3(BATCH / TM, SPLITK), NT, SMEM_BYTES>>>(x, idx1, idx2, idx3);

    int n4 = BATCH * C / 4;
    reduce_out<<<n4 / 256, 256>>>(bias, out);
}